// round 1
// baseline (speedup 1.0000x reference)
#include <cuda_runtime.h>
#include <cuda_bf16.h>

// Problem constants
#define NUM_EMB 4096
#define DIM     256
#define NROWS   65536                 // 16 * 4096
#define Q_ELEMS (NROWS * DIM)         // 16777216

// GEMM tiling
#define BM  128
#define BN  128
#define BKK 16
// 256 threads, 8x8 micro-tile per thread

// Scratch (no cudaMalloc allowed)
__device__ float g_half_sq[NUM_EMB];
__device__ int   g_best[NROWS];
__device__ float g_loss;

// ---------------------------------------------------------------------------
// Kernel 1: half squared norms of embeddings + zero the loss accumulator.
// One warp per embedding row (256 floats = 2 float4 per lane).
// ---------------------------------------------------------------------------
__global__ void vq_prep_kernel(const float* __restrict__ E) {
    if (blockIdx.x == 0 && threadIdx.x == 0) g_loss = 0.0f;
    int warp = (blockIdx.x * blockDim.x + threadIdx.x) >> 5;
    int lane = threadIdx.x & 31;
    if (warp >= NUM_EMB) return;
    const float4* row = (const float4*)(E + (size_t)warp * DIM);
    float s = 0.0f;
#pragma unroll
    for (int i = 0; i < 2; i++) {
        float4 v = row[lane + 32 * i];
        s += v.x * v.x + v.y * v.y + v.z * v.z + v.w * v.w;
    }
#pragma unroll
    for (int o = 16; o > 0; o >>= 1) s += __shfl_xor_sync(0xffffffffu, s, o);
    if (lane == 0) g_half_sq[warp] = 0.5f * s;
}

// ---------------------------------------------------------------------------
// Kernel 2: fused GEMM + argmax of (x.e - 0.5|e|^2) == argmin distance.
// Block tile: BM=128 rows x BN=128 embeddings, loop over all 4096 embeddings
// in chunks of BN. Classic register-blocked SGEMM with 8x8 micro-tiles.
// Ascending-index scan with strict '>' reproduces argmin first-occurrence
// tie-breaking.
// ---------------------------------------------------------------------------
__global__ __launch_bounds__(256, 2)
void vq_argmin_kernel(const float* __restrict__ X, const float* __restrict__ E,
                      float* __restrict__ out_idx_f) {
    __shared__ float As[BKK][BM];
    __shared__ float Bs[BKK][BN];
    __shared__ float hsS[BN];
    __shared__ float red_val[BM][17];   // +1 pad: conflict-free column scan
    __shared__ int   red_idx[BM][17];
    __shared__ float best_val[BM];
    __shared__ int   best_idx[BM];

    const int tid = threadIdx.x;
    const int tx = tid & 15;          // 16 col-groups
    const int ty = tid >> 4;          // 16 row-groups
    const int row0 = blockIdx.x * BM;

    if (tid < BM) { best_val[tid] = -3.402823e38f; best_idx[tid] = 0; }

    float acc[8][8];

    for (int nc = 0; nc < NUM_EMB; nc += BN) {
        if (tid < BN) hsS[tid] = g_half_sq[nc + tid];
#pragma unroll
        for (int i = 0; i < 8; i++)
#pragma unroll
            for (int j = 0; j < 8; j++) acc[i][j] = 0.0f;

        for (int kt = 0; kt < DIM; kt += BKK) {
            __syncthreads();   // smem tiles free to rewrite
            // Load A and B tiles (transposed into [BK][BM]); 2 float4 per
            // thread per tile. li in [0,512): r = li/4 rows, c4 = (li%4)*4.
#pragma unroll
            for (int it = 0; it < 2; it++) {
                int li = tid * 2 + it;
                int r  = li >> 2;
                int c4 = (li & 3) << 2;
                float4 va = *(const float4*)&X[(size_t)(row0 + r) * DIM + kt + c4];
                As[c4 + 0][r] = va.x; As[c4 + 1][r] = va.y;
                As[c4 + 2][r] = va.z; As[c4 + 3][r] = va.w;
                float4 vb = *(const float4*)&E[(size_t)(nc + r) * DIM + kt + c4];
                Bs[c4 + 0][r] = vb.x; Bs[c4 + 1][r] = vb.y;
                Bs[c4 + 2][r] = vb.z; Bs[c4 + 3][r] = vb.w;
            }
            __syncthreads();
#pragma unroll
            for (int k = 0; k < BKK; k++) {
                float4 a0 = *(const float4*)&As[k][ty * 8];
                float4 a1 = *(const float4*)&As[k][ty * 8 + 4];
                float4 b0 = *(const float4*)&Bs[k][tx * 8];
                float4 b1 = *(const float4*)&Bs[k][tx * 8 + 4];
                float a[8] = {a0.x, a0.y, a0.z, a0.w, a1.x, a1.y, a1.z, a1.w};
                float b[8] = {b0.x, b0.y, b0.z, b0.w, b1.x, b1.y, b1.z, b1.w};
#pragma unroll
                for (int i = 0; i < 8; i++)
#pragma unroll
                    for (int j = 0; j < 8; j++)
                        acc[i][j] += a[i] * b[j];
            }
        }
        __syncthreads();

        // Per-thread argmax over its 8 columns (ascending j -> lowest index
        // wins ties via strict '>').
#pragma unroll
        for (int i = 0; i < 8; i++) {
            float bv = -3.402823e38f;
            int   bj = 0;
#pragma unroll
            for (int j = 0; j < 8; j++) {
                float s = acc[i][j] - hsS[tx * 8 + j];
                if (s > bv) { bv = s; bj = j; }
            }
            red_val[ty * 8 + i][tx] = bv;
            red_idx[ty * 8 + i][tx] = nc + tx * 8 + bj;
        }
        __syncthreads();

        // Cross-thread reduce: one thread per row scans the 16 candidates in
        // ascending index order.
        if (tid < BM) {
            float bv = best_val[tid];
            int   bi = best_idx[tid];
#pragma unroll
            for (int t = 0; t < 16; t++) {
                float v = red_val[tid][t];
                if (v > bv) { bv = v; bi = red_idx[tid][t]; }
            }
            best_val[tid] = bv;
            best_idx[tid] = bi;
        }
        // no sync needed here: hsS rewrite (same tid<128 threads) and the
        // next kt-loop's leading __syncthreads order everything.
    }
    __syncthreads();
    if (tid < BM) {
        int bi = best_idx[tid];
        g_best[row0 + tid]     = bi;
        out_idx_f[row0 + tid]  = (float)bi;
    }
}

// ---------------------------------------------------------------------------
// Kernel 3: gather quantized rows + accumulate codebook loss.
// One warp per input row.
// ---------------------------------------------------------------------------
__global__ void vq_gather_kernel(const float* __restrict__ X,
                                 const float* __restrict__ E,
                                 float* __restrict__ outQ) {
    __shared__ float bsum[8];
    int warp = threadIdx.x >> 5;
    int lane = threadIdx.x & 31;
    int row = blockIdx.x * 8 + warp;
    int idx = g_best[row];
    const float4* e4 = (const float4*)(E + (size_t)idx * DIM);
    const float4* x4 = (const float4*)(X + (size_t)row * DIM);
    float4*       o4 = (float4*)(outQ + (size_t)row * DIM);
    float s = 0.0f;
#pragma unroll
    for (int i = 0; i < 2; i++) {
        float4 e = e4[lane + 32 * i];
        float4 x = x4[lane + 32 * i];
        o4[lane + 32 * i] = e;
        float dx = e.x - x.x, dy = e.y - x.y, dz = e.z - x.z, dw = e.w - x.w;
        s += dx * dx + dy * dy + dz * dz + dw * dw;
    }
#pragma unroll
    for (int o = 16; o > 0; o >>= 1) s += __shfl_xor_sync(0xffffffffu, s, o);
    if (lane == 0) bsum[warp] = s;
    __syncthreads();
    if (threadIdx.x == 0) {
        float t = 0.0f;
#pragma unroll
        for (int i = 0; i < 8; i++) t += bsum[i];
        atomicAdd(&g_loss, t);
    }
}

// ---------------------------------------------------------------------------
// Kernel 4: finalize loss = sum / (NROWS*DIM)
// ---------------------------------------------------------------------------
__global__ void vq_finalize_kernel(float* __restrict__ out_loss) {
    *out_loss = g_loss * (1.0f / (float)Q_ELEMS);
}

extern "C" void kernel_launch(void* const* d_in, const int* in_sizes, int n_in,
                              void* d_out, int out_size) {
    const float* X = (const float*)d_in[0];   // inputs [16,4096,256]
    const float* E = (const float*)d_in[1];   // embeddings [4096,256]
    float* out      = (float*)d_out;
    float* outQ     = out;                    // quantized_st: 16777216 floats
    float* outLoss  = out + Q_ELEMS;          // loss: 1 float
    float* outIdxF  = out + Q_ELEMS + 1;      // indices as float: 65536

    vq_prep_kernel<<<NUM_EMB / 8, 256>>>(E);
    vq_argmin_kernel<<<NROWS / BM, 256>>>(X, E, outIdxF);
    vq_gather_kernel<<<NROWS / 8, 256>>>(X, E, outQ);
    vq_finalize_kernel<<<1, 1>>>(outLoss);
}

// round 3
// speedup vs baseline: 1.9735x; 1.9735x over previous
#include <cuda_runtime.h>
#include <cuda_bf16.h>
#include <cstdint>

#define NUM_EMB 4096
#define DIM     256
#define NROWS   65536
#define Q_ELEMS (NROWS * DIM)
#define THRESH  3e-3f

#define BM 128
#define BN 128
#define BK 32
#define KITERS  24                 // 768 logical K / 32
#define NCHUNKS 32                 // 4096 / 128
#define TOTAL_ITERS (NCHUNKS * KITERS)

// ---- device scratch ----
__device__ __nv_bfloat16 g_Bbig[NUM_EMB * 512];   // [eh(256) | el(256)] per embedding
__device__ float g_half_sq[NUM_EMB];
__device__ int   g_best[NROWS];
__device__ int   g_flag_rows[NROWS];
__device__ int   g_flag_count;
__device__ float g_loss;

// ---- smem layout (dynamic) ----
#define SM_A     0
#define A_BYTES  (128 * 1024)       // 128 rows x 512 bf16 cols, swizzled
#define SM_B     A_BYTES
#define B_STAGE  8192               // 128 n x 32 k bf16
#define SM_HS    (SM_B + 3 * B_STAGE)
#define SMEM_TOTAL (SM_HS + 16384)  // 172032 B

__device__ __forceinline__ uint32_t smem_to_u32(const void* p) {
    uint32_t a;
    asm("{ .reg .u64 t; cvta.to.shared.u64 t, %1; cvt.u32.u64 %0, t; }" : "=r"(a) : "l"(p));
    return a;
}

#define LDSM_X4(r0, r1, r2, r3, addr) \
    asm volatile("ldmatrix.sync.aligned.m8n8.x4.shared.b16 {%0,%1,%2,%3}, [%4];" \
        : "=r"(r0), "=r"(r1), "=r"(r2), "=r"(r3) : "r"(addr))

#define MMA_BF16(d, a, b0, b1) \
    asm volatile("mma.sync.aligned.m16n8k16.row.col.f32.bf16.bf16.f32 " \
        "{%0,%1,%2,%3},{%4,%5,%6,%7},{%8,%9},{%0,%1,%2,%3};" \
        : "+f"((d)[0]), "+f"((d)[1]), "+f"((d)[2]), "+f"((d)[3]) \
        : "r"((a)[0]), "r"((a)[1]), "r"((a)[2]), "r"((a)[3]), "r"(b0), "r"(b1))

#define CP_ASYNC16(dst, src) \
    asm volatile("cp.async.cg.shared.global [%0], [%1], 16;" :: "r"(dst), "l"(src) : "memory")
#define CP_ASYNC_COMMIT() asm volatile("cp.async.commit_group;" ::: "memory")
#define CP_ASYNC_WAIT1()  asm volatile("cp.async.wait_group 1;" ::: "memory")

// ---------------------------------------------------------------------------
// prep: 0.5*|e|^2 + zero accumulators
// ---------------------------------------------------------------------------
__global__ void vq_prep_kernel(const float* __restrict__ E) {
    if (blockIdx.x == 0 && threadIdx.x == 0) { g_loss = 0.0f; g_flag_count = 0; }
    int warp = (blockIdx.x * blockDim.x + threadIdx.x) >> 5;
    int lane = threadIdx.x & 31;
    if (warp >= NUM_EMB) return;
    const float4* row = (const float4*)(E + (size_t)warp * DIM);
    float s = 0.0f;
#pragma unroll
    for (int i = 0; i < 2; i++) {
        float4 v = row[lane + 32 * i];
        s += v.x * v.x + v.y * v.y + v.z * v.z + v.w * v.w;
    }
#pragma unroll
    for (int o = 16; o > 0; o >>= 1) s += __shfl_xor_sync(0xffffffffu, s, o);
    if (lane == 0) g_half_sq[warp] = 0.5f * s;
}

// ---------------------------------------------------------------------------
// splitE: E fp32 -> g_Bbig [eh | el] bf16
// ---------------------------------------------------------------------------
__global__ void vq_splitE_kernel(const float* __restrict__ E) {
    int i = blockIdx.x * blockDim.x + threadIdx.x;   // over 4096*64 float4s
    if (i >= NUM_EMB * 64) return;
    int j = i >> 6, q = i & 63;
    float4 v = ((const float4*)E)[i];
    __nv_bfloat16 h[4], l[4];
    float f[4] = {v.x, v.y, v.z, v.w};
#pragma unroll
    for (int k = 0; k < 4; k++) {
        h[k] = __float2bfloat16(f[k]);
        l[k] = __float2bfloat16(f[k] - __bfloat162float(h[k]));
    }
    *(uint2*)(g_Bbig + (size_t)j * 512 + q * 4)       = *(uint2*)h;
    *(uint2*)(g_Bbig + (size_t)j * 512 + 256 + q * 4) = *(uint2*)l;
}

// ---------------------------------------------------------------------------
// main: fused bf16 mma.sync GEMM (K=768 logical) + top-2 argmax
// ---------------------------------------------------------------------------
__device__ __forceinline__ void load_B_stage(uint32_t sb, int stage, int chunk,
                                             int kt, int tid) {
    int kte = kt < 16 ? kt : kt - 16;
    const __nv_bfloat16* src0 = g_Bbig + (size_t)(chunk * BN) * 512 + kte * BK;
    uint32_t dstb = sb + SM_B + stage * B_STAGE;
#pragma unroll
    for (int j = 0; j < 2; j++) {
        int cid = tid + 256 * j;
        int n = cid >> 2, c = cid & 3;
        const void* src = src0 + (size_t)n * 512 + c * 8;
        uint32_t dst = dstb + (uint32_t)((n >> 1) * 128)
                     + ((uint32_t)(((((n & 1) << 2) | c) ^ ((n >> 1) & 7))) << 4);
        CP_ASYNC16(dst, src);
    }
}

__global__ __launch_bounds__(256, 1)
void vq_main_kernel(const float* __restrict__ X, float* __restrict__ out_idx_f) {
    extern __shared__ char smem[];
    uint32_t sb = smem_to_u32(smem);
    const int tid = threadIdx.x;
    const int l = tid & 31, wid = tid >> 5;
    const int wM = wid & 1, wN = wid >> 1;
    const int row0 = blockIdx.x * BM;

    // half_sq -> smem
    for (int i = tid; i < NUM_EMB / 4; i += 256)
        ((float4*)(smem + SM_HS))[i] = ((const float4*)g_half_sq)[i];

    // A fill: X fp32 -> smem [xh(0..31 chunks) | xl(32..63 chunks)], swizzled
    for (int i = tid; i < BM * 64; i += 256) {
        int row = i >> 6, q = i & 63;
        float4 v = ((const float4*)(X + (size_t)(row0 + row) * DIM))[q];
        __nv_bfloat16 h[4], lo[4];
        float f[4] = {v.x, v.y, v.z, v.w};
#pragma unroll
        for (int k = 0; k < 4; k++) {
            h[k]  = __float2bfloat16(f[k]);
            lo[k] = __float2bfloat16(f[k] - __bfloat162float(h[k]));
        }
        int rsw = row & 7;
        // hi at granule q, lo at granule 64+q  (granule = 8B = 4 bf16)
        {
            int g = q, c = g >> 1;
            uint32_t off = (uint32_t)row * 1024 + ((uint32_t)(c >> 3) << 7)
                         + ((uint32_t)((c & 7) ^ rsw) << 4) + ((uint32_t)(g & 1) << 3);
            *(uint2*)(smem + SM_A + off) = *(uint2*)h;
        }
        {
            int g = 64 + q, c = g >> 1;
            uint32_t off = (uint32_t)row * 1024 + ((uint32_t)(c >> 3) << 7)
                         + ((uint32_t)((c & 7) ^ rsw) << 4) + ((uint32_t)(g & 1) << 3);
            *(uint2*)(smem + SM_A + off) = *(uint2*)lo;
        }
    }

    // prefetch B stages for it = 0, 1
    load_B_stage(sb, 0, 0, 0, tid); CP_ASYNC_COMMIT();
    load_B_stage(sb, 1, 0, 1, tid); CP_ASYNC_COMMIT();

    // per-lane constants
    const int clA = l >> 4;          // 0/1 -> +8 in k
    const int lsw = l & 7;
    uint32_t abase[4];
#pragma unroll
    for (int mt = 0; mt < 4; mt++) {
        int rowA = wM * 64 + mt * 16 + (l & 15);
        abase[mt] = sb + SM_A + (uint32_t)rowA * 1024;
    }
    uint32_t bblk[2], bswz[2], bc4[2];
#pragma unroll
    for (int ntp = 0; ntp < 2; ntp++) {
        int nloc = wN * 32 + ntp * 16 + (l & 15);
        bblk[ntp] = (uint32_t)(nloc >> 1) * 128;
        bswz[ntp] = (uint32_t)((nloc >> 1) & 7);
        bc4[ntp]  = (uint32_t)((nloc & 1) << 2);
    }

    float acc[4][4][4];
#pragma unroll
    for (int a = 0; a < 4; a++)
#pragma unroll
        for (int b = 0; b < 4; b++)
#pragma unroll
            for (int c = 0; c < 4; c++) acc[a][b][c] = 0.0f;

    float b1[8], b2[8];
    int   idx1[8];
#pragma unroll
    for (int s = 0; s < 8; s++) { b1[s] = -3.402823e38f; b2[s] = -3.402823e38f; idx1[s] = 0; }

    int chunk = 0, kt = 0;
    int pf_chunk = 0, pf_kt = 2;     // prefetch target = it+2
    int buf = 0, pbuf = 2;
    const float* hsp = (const float*)(smem + SM_HS);

    for (int it = 0; it < TOTAL_ITERS; it++) {
        CP_ASYNC_WAIT1();
        __syncthreads();

        uint32_t bbuf = sb + SM_B + buf * B_STAGE;
        int ktp4 = kt * 4 - (kt >= 8 ? 32 : 0);   // phys chunk base in A (dedup wrap)
#pragma unroll
        for (int s = 0; s < 2; s++) {
            int cA = ktp4 + s * 2 + clA;
            uint32_t offA = ((uint32_t)(cA >> 3) << 7) | ((uint32_t)((cA & 7) ^ lsw) << 4);
            uint32_t a_[4][4];
#pragma unroll
            for (int mt = 0; mt < 4; mt++)
                LDSM_X4(a_[mt][0], a_[mt][1], a_[mt][2], a_[mt][3], abase[mt] + offA);
            uint32_t cB = (uint32_t)(s * 2 + clA);
            uint32_t bf[4][2];
#pragma unroll
            for (int ntp = 0; ntp < 2; ntp++) {
                uint32_t addr = bbuf + bblk[ntp] + (((bc4[ntp] | cB) ^ bswz[ntp]) << 4);
                uint32_t r0, r1, r2, r3;
                LDSM_X4(r0, r1, r2, r3, addr);
                bf[2 * ntp][0] = r0; bf[2 * ntp][1] = r2;
                bf[2 * ntp + 1][0] = r1; bf[2 * ntp + 1][1] = r3;
            }
#pragma unroll
            for (int mt = 0; mt < 4; mt++)
#pragma unroll
                for (int nt = 0; nt < 4; nt++)
                    MMA_BF16(acc[mt][nt], a_[mt], bf[nt][0], bf[nt][1]);
        }

        // prefetch it+2
        if (it + 2 < TOTAL_ITERS) {
            load_B_stage(sb, pbuf, pf_chunk, pf_kt, tid);
            if (++pf_kt == KITERS) { pf_kt = 0; pf_chunk++; }
        }
        CP_ASYNC_COMMIT();
        pbuf = (pbuf == 2) ? 0 : pbuf + 1;
        buf  = (buf == 2) ? 0 : buf + 1;

        if (kt == KITERS - 1) {
            // epilogue: scores -> running top-2
            int nbase = chunk * BN + wN * 32 + (l & 3) * 2;
#pragma unroll
            for (int mt = 0; mt < 4; mt++)
#pragma unroll
                for (int rh = 0; rh < 2; rh++) {
                    int slot = mt * 2 + rh;
                    float lb1 = b1[slot], lb2 = b2[slot];
                    int li = idx1[slot];
#pragma unroll
                    for (int nt = 0; nt < 4; nt++)
#pragma unroll
                        for (int cj = 0; cj < 2; cj++) {
                            int n = nbase + nt * 8 + cj;
                            float sc = acc[mt][nt][rh * 2 + cj] - hsp[n];
                            if (sc > lb1) { lb2 = lb1; lb1 = sc; li = n; }
                            else if (sc > lb2) lb2 = sc;
                        }
                    b1[slot] = lb1; b2[slot] = lb2; idx1[slot] = li;
                }
#pragma unroll
            for (int a = 0; a < 4; a++)
#pragma unroll
                for (int b = 0; b < 4; b++)
#pragma unroll
                    for (int c = 0; c < 4; c++) acc[a][b][c] = 0.0f;
            chunk++; kt = 0;
        } else kt++;
    }

    __syncthreads();   // done with B stages; reuse as reduce scratch

    // quad reduce (lanes sharing same rows: xor 1, 2)
#pragma unroll
    for (int d = 1; d <= 2; d <<= 1) {
#pragma unroll
        for (int s = 0; s < 8; s++) {
            float ov1 = __shfl_xor_sync(0xffffffffu, b1[s], d);
            float ov2 = __shfl_xor_sync(0xffffffffu, b2[s], d);
            int   oi  = __shfl_xor_sync(0xffffffffu, idx1[s], d);
            if (ov1 > b1[s]) { b2[s] = fmaxf(b1[s], ov2); b1[s] = ov1; idx1[s] = oi; }
            else             { b2[s] = fmaxf(b2[s], ov1); }
        }
    }
    float* rv1 = (float*)(smem + SM_B);
    float* rv2 = (float*)(smem + SM_B + 2048);
    int*   ri  = (int*)  (smem + SM_B + 4096);
    if ((l & 3) == 0) {
#pragma unroll
        for (int mt = 0; mt < 4; mt++)
#pragma unroll
            for (int rh = 0; rh < 2; rh++) {
                int slot = mt * 2 + rh;
                int row = wM * 64 + mt * 16 + (l >> 2) + rh * 8;
                rv1[row * 4 + wN] = b1[slot];
                rv2[row * 4 + wN] = b2[slot];
                ri [row * 4 + wN] = idx1[slot];
            }
    }
    __syncthreads();
    if (tid < BM) {
        float v1 = -3.402823e38f, v2 = -3.402823e38f;
        int bi = 0;
#pragma unroll
        for (int w = 0; w < 4; w++) {
            float w1 = rv1[tid * 4 + w], w2 = rv2[tid * 4 + w];
            int wi = ri[tid * 4 + w];
            if (w1 > v1) { v2 = fmaxf(v1, w2); v1 = w1; bi = wi; }
            else         { v2 = fmaxf(v2, w1); }
        }
        int grow = row0 + tid;
        g_best[grow] = bi;
        out_idx_f[grow] = (float)bi;
        if (v1 - v2 < THRESH) {
            int p = atomicAdd(&g_flag_count, 1);
            g_flag_rows[p] = grow;
        }
    }
}

// ---------------------------------------------------------------------------
// exact fp32 recompute for near-tie rows
// ---------------------------------------------------------------------------
__global__ void vq_fallback_kernel(const float* __restrict__ X,
                                   const float* __restrict__ E,
                                   float* __restrict__ out_idx_f) {
    __shared__ float xr[DIM];
    __shared__ float rv[256];
    __shared__ int   rix[256];
    int cnt = g_flag_count;
    for (int f = blockIdx.x; f < cnt; f += gridDim.x) {
        int row = g_flag_rows[f];
        __syncthreads();
        xr[threadIdx.x] = X[(size_t)row * DIM + threadIdx.x];
        __syncthreads();
        float bv = -3.402823e38f;
        int bi = 0;
        for (int j = threadIdx.x; j < NUM_EMB; j += 256) {
            const float4* e4 = (const float4*)(E + (size_t)j * DIM);
            float dot = 0.0f;
#pragma unroll
            for (int k = 0; k < 64; k++) {
                float4 e = e4[k];
                dot += xr[k * 4 + 0] * e.x + xr[k * 4 + 1] * e.y
                     + xr[k * 4 + 2] * e.z + xr[k * 4 + 3] * e.w;
            }
            float sc = dot - g_half_sq[j];
            if (sc > bv) { bv = sc; bi = j; }
        }
        rv[threadIdx.x] = bv; rix[threadIdx.x] = bi;
        __syncthreads();
        if (threadIdx.x == 0) {
            float fbv = rv[0]; int fbi = rix[0];
            for (int t = 1; t < 256; t++)
                if (rv[t] > fbv || (rv[t] == fbv && rix[t] < fbi)) { fbv = rv[t]; fbi = rix[t]; }
            g_best[row] = fbi;
            out_idx_f[row] = (float)fbi;
        }
        __syncthreads();
    }
}

// ---------------------------------------------------------------------------
// gather + codebook loss
// ---------------------------------------------------------------------------
__global__ void vq_gather_kernel(const float* __restrict__ X,
                                 const float* __restrict__ E,
                                 float* __restrict__ outQ) {
    __shared__ float bsum[8];
    int warp = threadIdx.x >> 5;
    int lane = threadIdx.x & 31;
    int row = blockIdx.x * 8 + warp;
    int idx = g_best[row];
    const float4* e4 = (const float4*)(E + (size_t)idx * DIM);
    const float4* x4 = (const float4*)(X + (size_t)row * DIM);
    float4*       o4 = (float4*)(outQ + (size_t)row * DIM);
    float s = 0.0f;
#pragma unroll
    for (int i = 0; i < 2; i++) {
        float4 e = e4[lane + 32 * i];
        float4 x = x4[lane + 32 * i];
        o4[lane + 32 * i] = e;
        float dx = e.x - x.x, dy = e.y - x.y, dz = e.z - x.z, dw = e.w - x.w;
        s += dx * dx + dy * dy + dz * dz + dw * dw;
    }
#pragma unroll
    for (int o = 16; o > 0; o >>= 1) s += __shfl_xor_sync(0xffffffffu, s, o);
    if (lane == 0) bsum[warp] = s;
    __syncthreads();
    if (threadIdx.x == 0) {
        float t = 0.0f;
#pragma unroll
        for (int i = 0; i < 8; i++) t += bsum[i];
        atomicAdd(&g_loss, t);
    }
}

__global__ void vq_finalize_kernel(float* __restrict__ out_loss) {
    *out_loss = g_loss * (1.0f / (float)Q_ELEMS);
}

extern "C" void kernel_launch(void* const* d_in, const int* in_sizes, int n_in,
                              void* d_out, int out_size) {
    const float* X = (const float*)d_in[0];
    const float* E = (const float*)d_in[1];
    float* out     = (float*)d_out;
    float* outQ    = out;
    float* outLoss = out + Q_ELEMS;
    float* outIdxF = out + Q_ELEMS + 1;

    cudaFuncSetAttribute(vq_main_kernel,
                         cudaFuncAttributeMaxDynamicSharedMemorySize, SMEM_TOTAL);

    vq_prep_kernel<<<NUM_EMB / 8, 256>>>(E);
    vq_splitE_kernel<<<NUM_EMB * 64 / 256, 256>>>(E);
    vq_main_kernel<<<NROWS / BM, 256, SMEM_TOTAL>>>(X, outIdxF);
    vq_fallback_kernel<<<256, 256>>>(X, E, outIdxF);
    vq_gather_kernel<<<NROWS / 8, 256>>>(X, E, outQ);
    vq_finalize_kernel<<<1, 1>>>(outLoss);
}